// round 8
// baseline (speedup 1.0000x reference)
#include <cuda_runtime.h>
#include <cstdint>

#define N 8192
#define IN_F 512
#define OUT_F 64
#define SS 512

// ---------------- device scratch (static) ----------------
__device__ __align__(16) float g_h[N * OUT_F];
__device__ __align__(16) float g_s1[N];
__device__ __align__(16) float g_s2[N];
__device__ __align__(16) double g_part[512 * N];   // 32MB per-block partial colsums
__device__ double g_colsum[N];
__device__ float  g_colsumf[N];

// ---------------- canary: prefill out (FLOAT this round) ----------------
__global__ void k_init(float* __restrict__ out) { out[threadIdx.x] = (float)threadIdx.x; }

// ---------------- h = input @ W (plain fp32, split accumulation) ----------------
// 256 threads = 4 rows x 64 cols; grid = N/4
__global__ void k_h(const float* __restrict__ in, const float* __restrict__ W) {
    int row = blockIdx.x * 4 + (threadIdx.x >> 6);
    int col = threadIdx.x & 63;
    const float* ir = in + (size_t)row * IN_F;
    float acc[8];
#pragma unroll
    for (int u = 0; u < 8; u++) acc[u] = 0.f;
#pragma unroll 4
    for (int m = 0; m < IN_F; m += 8) {
#pragma unroll
        for (int u = 0; u < 8; u++)
            acc[u] = fmaf(__ldg(ir + m + u), __ldg(W + (m + u) * OUT_F + col), acc[u]);
    }
    g_h[row * OUT_F + col] = ((acc[0] + acc[1]) + (acc[2] + acc[3]))
                           + ((acc[4] + acc[5]) + (acc[6] + acc[7]));
}

// ---------------- s1 = h@a1, s2 = h@a2 ----------------
// warp per node; grid = N/8
__global__ void k_params(const float* __restrict__ a) {
    int lane = threadIdx.x & 31;
    int node = blockIdx.x * 8 + (threadIdx.x >> 5);
    const float* hr = g_h + node * OUT_F;
    float h0 = hr[lane], h1 = hr[32 + lane];
    float s1 = h0 * __ldg(a + lane)         + h1 * __ldg(a + 32 + lane);
    float s2 = h0 * __ldg(a + OUT_F + lane) + h1 * __ldg(a + OUT_F + 32 + lane);
#pragma unroll
    for (int o = 16; o; o >>= 1) {
        s1 += __shfl_xor_sync(0xFFFFFFFFu, s1, o);
        s2 += __shfl_xor_sync(0xFFFFFFFFu, s2, o);
    }
    if (lane == 0) { g_s1[node] = s1; g_s2[node] = s2; }
}

// ---------------- LITERAL masked softmax + column sums (fp64 accumulation) ---
// 512 blocks x 512 threads; block owns 16 rows; thread owns 16 fixed columns
//   column(g,e) = g*2048 + 4t + e
//   e   = leaky_relu(s1_i + s2_j)   [lrelu(x) == fmaxf(x, 0.2f*x), exact]
//   w   = adj>0 ? exp(e) : 0
//   att = w / sum_j(w)              [fp64 sum and divide]
//   colsum_j += att                 [fp64]
__global__ void __launch_bounds__(512, 1) k_main(const int* __restrict__ adj) {
    __shared__ double sZ[2][16];
    int t = threadIdx.x;
    int warp = t >> 5, lane = t & 31;
    int row0 = blockIdx.x * 16;

    float s2r[16];
    const float4* s2v = (const float4*)g_s2;
#pragma unroll
    for (int g = 0; g < 4; g++) {
        float4 v = __ldg(s2v + g * 512 + t);
        s2r[g * 4 + 0] = v.x; s2r[g * 4 + 1] = v.y;
        s2r[g * 4 + 2] = v.z; s2r[g * 4 + 3] = v.w;
    }

    double acc[16];
#pragma unroll
    for (int k = 0; k < 16; k++) acc[k] = 0.0;

    int4 a4[4];
#pragma unroll
    for (int g = 0; g < 4; g++)
        a4[g] = __ldg((const int4*)(adj + (size_t)row0 * N) + g * 512 + t);

    for (int r = 0; r < 16; r++) {
        float s1 = __ldg(g_s1 + row0 + r);
        float w[16];
        double z = 0.0;
#pragma unroll
        for (int g = 0; g < 4; g++) {
            int4 A = a4[g];
#pragma unroll
            for (int e = 0; e < 4; e++) {
                float x  = s1 + s2r[g * 4 + e];
                float lr = fmaxf(x, 0.2f * x);          // exact leaky_relu
                int   m  = (e == 0) ? A.x : (e == 1) ? A.y : (e == 2) ? A.z : A.w;
                float ww = (m > 0) ? __expf(lr) : 0.f;
                w[g * 4 + e] = ww;
                z += (double)ww;
            }
        }
        if (r < 15) {
            const int4* nb = (const int4*)(adj + (size_t)(row0 + r + 1) * N);
#pragma unroll
            for (int g = 0; g < 4; g++) a4[g] = __ldg(nb + g * 512 + t);
        }
#pragma unroll
        for (int o = 16; o; o >>= 1) z += __shfl_xor_sync(0xFFFFFFFFu, z, o);
        if (lane == 0) sZ[r & 1][warp] = z;
        __syncthreads();
        double zt = 0.0;
#pragma unroll
        for (int q = 0; q < 16; q++) zt += sZ[r & 1][q];
        double invZ = (zt > 0.0) ? (1.0 / zt) : 0.0;
#pragma unroll
        for (int k = 0; k < 16; k++) acc[k] += (double)w[k] * invZ;
    }

    double2* p2 = (double2*)(g_part + (size_t)blockIdx.x * N);
#pragma unroll
    for (int g = 0; g < 4; g++) {
        p2[g * 1024 + 2 * t + 0] = make_double2(acc[g * 4 + 0], acc[g * 4 + 1]);
        p2[g * 1024 + 2 * t + 1] = make_double2(acc[g * 4 + 2], acc[g * 4 + 3]);
    }
}

// ---------------- deterministic fixed-order fp64 column reduction ----------------
__global__ void k_reduce() {
    int c = blockIdx.x * blockDim.x + threadIdx.x;
    double s = 0.0;
    for (int b = 0; b < 512; b++) s += g_part[(size_t)b * N + c];
    g_colsum[c] = s;
    g_colsumf[c] = (float)s;
}

// ---------------- exact top-512 via brute-force ranking (FLOAT out) ----------------
// rank(j) = #{j': s>s_j} + #{j'<j: s==s_j}; uint bit-compare (scores >= 0).
// Ranks are a bijection onto 0..N-1, so out[0..511] each written exactly once.
__global__ void __launch_bounds__(256) k_rank(float* __restrict__ out) {
    __shared__ uint32_t sc[N];
    __shared__ int sr[256];
    int t = threadIdx.x;
#pragma unroll
    for (int p = 0; p < N / 256; p++)
        sc[p * 256 + t] = __float_as_uint(g_colsumf[p * 256 + t]);
    __syncthreads();

    int jl  = t & 31;
    int seg = t >> 5;
    int j = blockIdx.x * 32 + jl;
    uint32_t sj = sc[j];
    int rank = 0;
    int p0 = seg * (N / 8);
#pragma unroll 4
    for (int p = p0; p < p0 + N / 8; p++) {
        uint32_t sp = sc[p];
        rank += (sp > sj) || (sp == sj && p < j);
    }
    sr[t] = rank;
    __syncthreads();
    if (t < 32) {
        int total = 0;
#pragma unroll
        for (int s = 0; s < 8; s++) total += sr[t + 32 * s];
        if (total < SS) out[total] = (float)j;    // <-- FLOAT index, exact for j<2^24
    }
}

// ---------------- launch ----------------
extern "C" void kernel_launch(void* const* d_in, const int* in_sizes, int n_in,
                              void* d_out, int out_size) {
    const float* input = nullptr;
    const int*   adj   = nullptr;
    const float* W     = nullptr;
    const float* a     = nullptr;
    for (int i = 0; i < n_in; i++) {
        long long s = in_sizes[i];
        if      (s == (long long)N * IN_F)     input = (const float*)d_in[i];
        else if (s == (long long)N * N)        adj   = (const int*)d_in[i];
        else if (s == (long long)IN_F * OUT_F) W     = (const float*)d_in[i];
        else if (s == 2 * OUT_F)               a     = (const float*)d_in[i];
    }
    if (!input || !adj || !W || !a) {
        input = (const float*)d_in[0];
        adj   = (const int*)d_in[1];
        W     = (const float*)d_in[2];
        a     = (const float*)d_in[3];
    }
    float* out = (float*)d_out;

    k_init<<<1, SS>>>(out);
    k_h<<<N / 4, 256>>>(input, W);
    k_params<<<N / 8, 256>>>(a);
    k_main<<<512, 512>>>(adj);
    k_reduce<<<N / 256, 256>>>();
    k_rank<<<256, 256>>>(out);
}

// round 9
// speedup vs baseline: 2.9107x; 2.9107x over previous
#include <cuda_runtime.h>
#include <cstdint>

#define N 8192
#define IN_F 512
#define OUT_F 64
#define SS 512

// ---------------- device scratch (static) ----------------
__device__ __align__(16) float g_h[N * OUT_F];
__device__ float g_R[N];                           // exp(-0.8 * s1_i)
__device__ __align__(16) float2 g_EP[N];           // (exp(s2_j), exp(0.2*s2_j))
__device__ __align__(16) float g_part[512 * N];    // 16MB per-block partial colsums
__device__ float g_colsumf[N];

// ---------------- h = input @ W (fp32, split accumulation) ----------------
// 256 threads = 4 rows x 64 cols; grid = N/4
__global__ void k_h(const float* __restrict__ in, const float* __restrict__ W) {
    int row = blockIdx.x * 4 + (threadIdx.x >> 6);
    int col = threadIdx.x & 63;
    const float* ir = in + (size_t)row * IN_F;
    float acc[8];
#pragma unroll
    for (int u = 0; u < 8; u++) acc[u] = 0.f;
#pragma unroll 4
    for (int m = 0; m < IN_F; m += 8) {
#pragma unroll
        for (int u = 0; u < 8; u++)
            acc[u] = fmaf(__ldg(ir + m + u), __ldg(W + (m + u) * OUT_F + col), acc[u]);
    }
    g_h[row * OUT_F + col] = ((acc[0] + acc[1]) + (acc[2] + acc[3]))
                           + ((acc[4] + acc[5]) + (acc[6] + acc[7]));
}

// ---------------- per-node scalars: R_i, (ex_j, ey_j), exp in double ----------------
// warp per node; grid = N/8
__global__ void k_params(const float* __restrict__ a) {
    int lane = threadIdx.x & 31;
    int node = blockIdx.x * 8 + (threadIdx.x >> 5);
    const float* hr = g_h + node * OUT_F;
    float h0 = hr[lane], h1 = hr[32 + lane];
    float s1 = h0 * __ldg(a + lane)         + h1 * __ldg(a + 32 + lane);
    float s2 = h0 * __ldg(a + OUT_F + lane) + h1 * __ldg(a + OUT_F + 32 + lane);
#pragma unroll
    for (int o = 16; o; o >>= 1) {
        s1 += __shfl_xor_sync(0xFFFFFFFFu, s1, o);
        s2 += __shfl_xor_sync(0xFFFFFFFFu, s2, o);
    }
    if (lane == 0) {
        double d1 = (double)s1, d2 = (double)s2;
        g_R[node] = (float)exp(-0.8 * d1);
        g_EP[node] = make_float2((float)exp(d2), (float)exp(0.2 * d2));
    }
}

// ---------------- factorized masked-softmax + column partial sums ----------------
// 512 blocks x 512 threads; block owns 16 rows; thread owns 16 fixed columns:
//   column(g,e) = g*2048 + 4t + e  -> coalesced int4 adj loads
// exp(lrelu(s1+s2) - s1) = max(exp(s2), exp(-0.8*s1)*exp(0.2*s2)) = max(ex, R*ey)
// (shift by s1 is exact softmax invariance; verified against the literal R8 kernel)
__global__ void __launch_bounds__(512, 1) k_main(const int* __restrict__ adj) {
    __shared__ float sZ[2][16];
    int t = threadIdx.x;
    int warp = t >> 5, lane = t & 31;
    int row0 = blockIdx.x * 16;

    // this thread's 16 (ex, ey) pairs -> registers
    float ex[16], ey[16];
    const float4* ep4 = (const float4*)g_EP;       // one float4 = 2 nodes
#pragma unroll
    for (int g = 0; g < 4; g++) {
#pragma unroll
        for (int q = 0; q < 2; q++) {
            float4 v = __ldg(ep4 + g * 1024 + 2 * t + q);
            ex[g * 4 + 2 * q + 0] = v.x; ey[g * 4 + 2 * q + 0] = v.y;
            ex[g * 4 + 2 * q + 1] = v.z; ey[g * 4 + 2 * q + 1] = v.w;
        }
    }

    float acc[16];
#pragma unroll
    for (int k = 0; k < 16; k++) acc[k] = 0.f;

    // prefetch row 0 adjacency
    int4 a4[4];
#pragma unroll
    for (int g = 0; g < 4; g++)
        a4[g] = __ldg((const int4*)(adj + (size_t)row0 * N) + g * 512 + t);

    for (int r = 0; r < 16; r++) {
        float R = __ldg(g_R + row0 + r);
        float w[16];
        float z = 0.f;
#pragma unroll
        for (int g = 0; g < 4; g++) {
            int4 A = a4[g];
            float w0 = fmaxf(ex[g * 4 + 0], R * ey[g * 4 + 0]);
            float w1 = fmaxf(ex[g * 4 + 1], R * ey[g * 4 + 1]);
            float w2 = fmaxf(ex[g * 4 + 2], R * ey[g * 4 + 2]);
            float w3 = fmaxf(ex[g * 4 + 3], R * ey[g * 4 + 3]);
            w0 = (A.x > 0) ? w0 : 0.f;
            w1 = (A.y > 0) ? w1 : 0.f;
            w2 = (A.z > 0) ? w2 : 0.f;
            w3 = (A.w > 0) ? w3 : 0.f;
            w[g * 4 + 0] = w0; w[g * 4 + 1] = w1;
            w[g * 4 + 2] = w2; w[g * 4 + 3] = w3;
            z += (w0 + w1) + (w2 + w3);            // pairwise within group
        }
        // prefetch next row before the barrier
        if (r < 15) {
            const int4* nb = (const int4*)(adj + (size_t)(row0 + r + 1) * N);
#pragma unroll
            for (int g = 0; g < 4; g++) a4[g] = __ldg(nb + g * 512 + t);
        }
        // block-wide row sum (double-buffered, one barrier per row)
#pragma unroll
        for (int o = 16; o; o >>= 1) z += __shfl_xor_sync(0xFFFFFFFFu, z, o);
        if (lane == 0) sZ[r & 1][warp] = z;
        __syncthreads();
        float zt = 0.f;
#pragma unroll
        for (int q = 0; q < 16; q++) zt += sZ[r & 1][q];
        float invZ = (zt > 0.f) ? (1.0f / zt) : 0.f;
#pragma unroll
        for (int k = 0; k < 16; k++) acc[k] = fmaf(w[k], invZ, acc[k]);
    }

    // coalesced float4 stores of 16 partials
    float4* part4 = (float4*)(g_part + (size_t)blockIdx.x * N);
#pragma unroll
    for (int g = 0; g < 4; g++)
        part4[g * 512 + t] = make_float4(acc[g * 4 + 0], acc[g * 4 + 1],
                                         acc[g * 4 + 2], acc[g * 4 + 3]);
}

// ---------------- deterministic fixed-order fp64 column reduction ----------------
__global__ void k_reduce() {
    int c = blockIdx.x * blockDim.x + threadIdx.x;
    double s = 0.0;
    for (int b = 0; b < 512; b++) s += (double)g_part[(size_t)b * N + c];
    g_colsumf[c] = (float)s;
}

// ---------------- exact top-512 via brute-force ranking (FLOAT out) ----------------
// rank(j) = #{j': s>s_j} + #{j'<j: s==s_j}; uint bit-compare (scores >= 0).
__global__ void __launch_bounds__(256) k_rank(float* __restrict__ out) {
    __shared__ uint32_t sc[N];
    __shared__ int sr[256];
    int t = threadIdx.x;
#pragma unroll
    for (int p = 0; p < N / 256; p++)
        sc[p * 256 + t] = __float_as_uint(g_colsumf[p * 256 + t]);
    __syncthreads();

    int jl  = t & 31;
    int seg = t >> 5;
    int j = blockIdx.x * 32 + jl;
    uint32_t sj = sc[j];
    int rank = 0;
    int p0 = seg * (N / 8);
#pragma unroll 4
    for (int p = p0; p < p0 + N / 8; p++) {
        uint32_t sp = sc[p];
        rank += (sp > sj) || (sp == sj && p < j);
    }
    sr[t] = rank;
    __syncthreads();
    if (t < 32) {
        int total = 0;
#pragma unroll
        for (int s = 0; s < 8; s++) total += sr[t + 32 * s];
        if (total < SS) out[total] = (float)j;     // float index, exact for j < 2^24
    }
}

// ---------------- launch ----------------
extern "C" void kernel_launch(void* const* d_in, const int* in_sizes, int n_in,
                              void* d_out, int out_size) {
    const float* input = nullptr;
    const int*   adj   = nullptr;
    const float* W     = nullptr;
    const float* a     = nullptr;
    for (int i = 0; i < n_in; i++) {
        long long s = in_sizes[i];
        if      (s == (long long)N * IN_F)     input = (const float*)d_in[i];
        else if (s == (long long)N * N)        adj   = (const int*)d_in[i];
        else if (s == (long long)IN_F * OUT_F) W     = (const float*)d_in[i];
        else if (s == 2 * OUT_F)               a     = (const float*)d_in[i];
    }
    if (!input || !adj || !W || !a) {
        input = (const float*)d_in[0];
        adj   = (const int*)d_in[1];
        W     = (const float*)d_in[2];
        a     = (const float*)d_in[3];
    }
    float* out = (float*)d_out;

    k_h<<<N / 4, 256>>>(input, W);
    k_params<<<N / 8, 256>>>(a);
    k_main<<<512, 512>>>(adj);
    k_reduce<<<N / 256, 256>>>();
    k_rank<<<256, 256>>>(out);
}

// round 10
// speedup vs baseline: 5.0414x; 1.7320x over previous
#include <cuda_runtime.h>
#include <cstdint>

#define N 8192
#define IN_F 512
#define OUT_F 64
#define SS 512

// ---------------- device scratch (static) ----------------
__device__ float g_wa[2 * IN_F];                   // wa1[512], wa2[512]
__device__ float g_R[N];                           // exp(-0.8 * s1_i)
__device__ __align__(16) float2 g_EP[N];           // (exp(s2_j), exp(0.2*s2_j))
__device__ __align__(16) float g_part[512 * N];    // 16MB per-block partial colsums
__device__ float g_colsumf[N];

// ---------------- wa1 = W @ a1, wa2 = W @ a2 (tiny: 65K MACs) ----------------
// 1 block, 512 threads; thread m owns W row m (contiguous, float4-vectorized)
__global__ void k_wa(const float* __restrict__ W, const float* __restrict__ a) {
    int m = threadIdx.x;
    const float4* w4 = (const float4*)(W + m * OUT_F);
    float s1 = 0.f, s2 = 0.f;
#pragma unroll
    for (int q = 0; q < OUT_F / 4; q++) {
        float4 wv = __ldg(w4 + q);
        s1 += wv.x * __ldg(a + 4 * q + 0) + wv.y * __ldg(a + 4 * q + 1)
            + wv.z * __ldg(a + 4 * q + 2) + wv.w * __ldg(a + 4 * q + 3);
        s2 += wv.x * __ldg(a + OUT_F + 4 * q + 0) + wv.y * __ldg(a + OUT_F + 4 * q + 1)
            + wv.z * __ldg(a + OUT_F + 4 * q + 2) + wv.w * __ldg(a + OUT_F + 4 * q + 3);
    }
    g_wa[m] = s1;
    g_wa[IN_F + m] = s2;
}

// ---------------- s1,s2 = input @ wa  ->  R_i, (ex_j, ey_j) ----------------
// warp per row; 256 threads = 8 rows/block; grid = N/8; reads input 16MB once
__global__ void k_s(const float* __restrict__ in) {
    __shared__ float swa[2 * IN_F];
    int t = threadIdx.x;
#pragma unroll
    for (int q = 0; q < 4; q++) swa[q * 256 + t] = g_wa[q * 256 + t];
    __syncthreads();

    int warp = t >> 5, lane = t & 31;
    int row = blockIdx.x * 8 + warp;
    const float* ir = in + (size_t)row * IN_F;
    float s1 = 0.f, s2 = 0.f;
#pragma unroll
    for (int q = 0; q < IN_F / 32; q++) {
        float x = __ldg(ir + q * 32 + lane);       // warp-coalesced
        s1 = fmaf(x, swa[q * 32 + lane], s1);      // conflict-free LDS
        s2 = fmaf(x, swa[IN_F + q * 32 + lane], s2);
    }
#pragma unroll
    for (int o = 16; o; o >>= 1) {
        s1 += __shfl_xor_sync(0xFFFFFFFFu, s1, o);
        s2 += __shfl_xor_sync(0xFFFFFFFFu, s2, o);
    }
    if (lane == 0) {
        double d1 = (double)s1, d2 = (double)s2;
        g_R[row] = (float)exp(-0.8 * d1);
        g_EP[row] = make_float2((float)exp(d2), (float)exp(0.2 * d2));
    }
}

// ---------------- factorized masked-softmax + column partial sums ----------------
// 512 blocks x 512 threads; block owns 16 rows; thread owns 16 fixed columns:
//   column(g,e) = g*2048 + 4t + e  -> coalesced int4 adj loads
// exp(lrelu(s1+s2) - s1) = max(ex_j, R_i*ey_j)   [exact softmax shift invariance]
__global__ void __launch_bounds__(512, 1) k_main(const int* __restrict__ adj) {
    __shared__ float sZ[2][16];
    int t = threadIdx.x;
    int warp = t >> 5, lane = t & 31;
    int row0 = blockIdx.x * 16;

    float ex[16], ey[16];
    const float4* ep4 = (const float4*)g_EP;       // one float4 = 2 nodes
#pragma unroll
    for (int g = 0; g < 4; g++) {
#pragma unroll
        for (int q = 0; q < 2; q++) {
            float4 v = __ldg(ep4 + g * 1024 + 2 * t + q);
            ex[g * 4 + 2 * q + 0] = v.x; ey[g * 4 + 2 * q + 0] = v.y;
            ex[g * 4 + 2 * q + 1] = v.z; ey[g * 4 + 2 * q + 1] = v.w;
        }
    }

    float acc[16];
#pragma unroll
    for (int k = 0; k < 16; k++) acc[k] = 0.f;

    int4 a4[4];
#pragma unroll
    for (int g = 0; g < 4; g++)
        a4[g] = __ldg((const int4*)(adj + (size_t)row0 * N) + g * 512 + t);

    for (int r = 0; r < 16; r++) {
        float R = __ldg(g_R + row0 + r);
        float w[16];
        float z = 0.f;
#pragma unroll
        for (int g = 0; g < 4; g++) {
            int4 A = a4[g];
            float w0 = fmaxf(ex[g * 4 + 0], R * ey[g * 4 + 0]);
            float w1 = fmaxf(ex[g * 4 + 1], R * ey[g * 4 + 1]);
            float w2 = fmaxf(ex[g * 4 + 2], R * ey[g * 4 + 2]);
            float w3 = fmaxf(ex[g * 4 + 3], R * ey[g * 4 + 3]);
            w0 = (A.x > 0) ? w0 : 0.f;
            w1 = (A.y > 0) ? w1 : 0.f;
            w2 = (A.z > 0) ? w2 : 0.f;
            w3 = (A.w > 0) ? w3 : 0.f;
            w[g * 4 + 0] = w0; w[g * 4 + 1] = w1;
            w[g * 4 + 2] = w2; w[g * 4 + 3] = w3;
            z += (w0 + w1) + (w2 + w3);
        }
        if (r < 15) {
            const int4* nb = (const int4*)(adj + (size_t)(row0 + r + 1) * N);
#pragma unroll
            for (int g = 0; g < 4; g++) a4[g] = __ldg(nb + g * 512 + t);
        }
#pragma unroll
        for (int o = 16; o; o >>= 1) z += __shfl_xor_sync(0xFFFFFFFFu, z, o);
        if (lane == 0) sZ[r & 1][warp] = z;
        __syncthreads();
        float zt = 0.f;
#pragma unroll
        for (int q = 0; q < 16; q++) zt += sZ[r & 1][q];
        float invZ = (zt > 0.f) ? (1.0f / zt) : 0.f;
#pragma unroll
        for (int k = 0; k < 16; k++) acc[k] = fmaf(w[k], invZ, acc[k]);
    }

    float4* part4 = (float4*)(g_part + (size_t)blockIdx.x * N);
#pragma unroll
    for (int g = 0; g < 4; g++)
        part4[g * 512 + t] = make_float4(acc[g * 4 + 0], acc[g * 4 + 1],
                                         acc[g * 4 + 2], acc[g * 4 + 3]);
}

// ---------------- parallel deterministic fp64 column reduction ----------------
// 256 blocks x 256 threads. Block owns 32 columns; 8 chunk-threads per column,
// each sums 64 partials serially (fp64), then fixed-order combine -> deterministic.
__global__ void __launch_bounds__(256) k_reduce() {
    __shared__ double sd[8][32];
    int t = threadIdx.x;
    int v = t & 31;            // column within block
    int u = t >> 5;            // chunk 0..7
    int c = blockIdx.x * 32 + v;
    double s = 0.0;
    int b0 = u * 64;
#pragma unroll 4
    for (int b = b0; b < b0 + 64; b++)
        s += (double)g_part[(size_t)b * N + c];    // warp-coalesced (consecutive c)
    sd[u][v] = s;
    __syncthreads();
    if (u == 0) {
        double tot = 0.0;
#pragma unroll
        for (int q = 0; q < 8; q++) tot += sd[q][v];   // fixed order
        g_colsumf[c] = (float)tot;
    }
}

// ---------------- exact top-512 via brute-force ranking (FLOAT out) ----------------
__global__ void __launch_bounds__(256) k_rank(float* __restrict__ out) {
    __shared__ uint32_t sc[N];
    __shared__ int sr[256];
    int t = threadIdx.x;
#pragma unroll
    for (int p = 0; p < N / 256; p++)
        sc[p * 256 + t] = __float_as_uint(g_colsumf[p * 256 + t]);
    __syncthreads();

    int jl  = t & 31;
    int seg = t >> 5;
    int j = blockIdx.x * 32 + jl;
    uint32_t sj = sc[j];
    int rank = 0;
    int p0 = seg * (N / 8);
#pragma unroll 4
    for (int p = p0; p < p0 + N / 8; p++) {
        uint32_t sp = sc[p];
        rank += (sp > sj) || (sp == sj && p < j);
    }
    sr[t] = rank;
    __syncthreads();
    if (t < 32) {
        int total = 0;
#pragma unroll
        for (int s = 0; s < 8; s++) total += sr[t + 32 * s];
        if (total < SS) out[total] = (float)j;     // float index (output dtype is f32)
    }
}

// ---------------- launch ----------------
extern "C" void kernel_launch(void* const* d_in, const int* in_sizes, int n_in,
                              void* d_out, int out_size) {
    const float* input = nullptr;
    const int*   adj   = nullptr;
    const float* W     = nullptr;
    const float* a     = nullptr;
    for (int i = 0; i < n_in; i++) {
        long long s = in_sizes[i];
        if      (s == (long long)N * IN_F)     input = (const float*)d_in[i];
        else if (s == (long long)N * N)        adj   = (const int*)d_in[i];
        else if (s == (long long)IN_F * OUT_F) W     = (const float*)d_in[i];
        else if (s == 2 * OUT_F)               a     = (const float*)d_in[i];
    }
    if (!input || !adj || !W || !a) {
        input = (const float*)d_in[0];
        adj   = (const int*)d_in[1];
        W     = (const float*)d_in[2];
        a     = (const float*)d_in[3];
    }
    float* out = (float*)d_out;

    k_wa<<<1, IN_F>>>(W, a);
    k_s<<<N / 8, 256>>>(input);
    k_main<<<512, 512>>>(adj);
    k_reduce<<<N / 32, 256>>>();
    k_rank<<<256, 256>>>(out);
}

// round 11
// speedup vs baseline: 5.9463x; 1.1795x over previous
#include <cuda_runtime.h>
#include <cstdint>

#define N 8192
#define IN_F 512
#define OUT_F 64
#define SS 512

// ---------------- device scratch (static) ----------------
__device__ float g_wa[2 * IN_F];                   // wa1[512], wa2[512]
__device__ float g_R[N];                           // exp(-0.8 * s1_i)
__device__ __align__(16) float2 g_EP[N];           // (exp(s2_j), exp(0.2*s2_j))
__device__ __align__(16) float g_part[512 * N];    // 16MB per-block partial colsums
__device__ float g_colsumf[N];

// ---------------- wa1 = W @ a1, wa2 = W @ a2 (tiny) ----------------
__global__ void k_wa(const float* __restrict__ W, const float* __restrict__ a) {
    int m = threadIdx.x;
    const float4* w4 = (const float4*)(W + m * OUT_F);
    float s1 = 0.f, s2 = 0.f;
#pragma unroll
    for (int q = 0; q < OUT_F / 4; q++) {
        float4 wv = __ldg(w4 + q);
        s1 += wv.x * __ldg(a + 4 * q + 0) + wv.y * __ldg(a + 4 * q + 1)
            + wv.z * __ldg(a + 4 * q + 2) + wv.w * __ldg(a + 4 * q + 3);
        s2 += wv.x * __ldg(a + OUT_F + 4 * q + 0) + wv.y * __ldg(a + OUT_F + 4 * q + 1)
            + wv.z * __ldg(a + OUT_F + 4 * q + 2) + wv.w * __ldg(a + OUT_F + 4 * q + 3);
    }
    g_wa[m] = s1;
    g_wa[IN_F + m] = s2;
}

// ---------------- s1,s2 = input @ wa  ->  R_i, (ex_j, ey_j) ----------------
// warp per row; grid = N/8; reads input (16MB) once
__global__ void k_s(const float* __restrict__ in) {
    __shared__ float swa[2 * IN_F];
    int t = threadIdx.x;
#pragma unroll
    for (int q = 0; q < 4; q++) swa[q * 256 + t] = g_wa[q * 256 + t];
    __syncthreads();

    int warp = t >> 5, lane = t & 31;
    int row = blockIdx.x * 8 + warp;
    const float* ir = in + (size_t)row * IN_F;
    float s1 = 0.f, s2 = 0.f;
#pragma unroll
    for (int q = 0; q < IN_F / 32; q++) {
        float x = __ldg(ir + q * 32 + lane);
        s1 = fmaf(x, swa[q * 32 + lane], s1);
        s2 = fmaf(x, swa[IN_F + q * 32 + lane], s2);
    }
#pragma unroll
    for (int o = 16; o; o >>= 1) {
        s1 += __shfl_xor_sync(0xFFFFFFFFu, s1, o);
        s2 += __shfl_xor_sync(0xFFFFFFFFu, s2, o);
    }
    if (lane == 0) {
        double d1 = (double)s1, d2 = (double)s2;
        g_R[row] = (float)exp(-0.8 * d1);
        g_EP[row] = make_float2((float)exp(d2), (float)exp(0.2 * d2));
    }
}

// ---------------- factorized masked-softmax + column partial sums ----------------
// 512 blocks x 512 threads; block owns 16 rows; thread owns 16 fixed columns.
// DEPTH-2 adjacency prefetch: 8 LDG.128 in flight per warp -> saturate LTS.
__global__ void __launch_bounds__(512, 1) k_main(const int* __restrict__ adj) {
    __shared__ float sZ[2][16];
    int t = threadIdx.x;
    int warp = t >> 5, lane = t & 31;
    int row0 = blockIdx.x * 16;

    float ex[16], ey[16];
    const float4* ep4 = (const float4*)g_EP;       // one float4 = 2 nodes
#pragma unroll
    for (int g = 0; g < 4; g++) {
#pragma unroll
        for (int q = 0; q < 2; q++) {
            float4 v = __ldg(ep4 + g * 1024 + 2 * t + q);
            ex[g * 4 + 2 * q + 0] = v.x; ey[g * 4 + 2 * q + 0] = v.y;
            ex[g * 4 + 2 * q + 1] = v.z; ey[g * 4 + 2 * q + 1] = v.w;
        }
    }

    float acc[16];
#pragma unroll
    for (int k = 0; k < 16; k++) acc[k] = 0.f;

    // double-buffered adjacency prefetch (rows r and r+1 in flight)
    int4 a4[2][4];
#pragma unroll
    for (int g = 0; g < 4; g++) {
        a4[0][g] = __ldg((const int4*)(adj + (size_t)(row0 + 0) * N) + g * 512 + t);
        a4[1][g] = __ldg((const int4*)(adj + (size_t)(row0 + 1) * N) + g * 512 + t);
    }

    for (int r = 0; r < 16; r++) {
        float R = __ldg(g_R + row0 + r);
        float w[16];
        float z = 0.f;
#pragma unroll
        for (int g = 0; g < 4; g++) {
            int4 A = a4[r & 1][g];
            float w0 = fmaxf(ex[g * 4 + 0], R * ey[g * 4 + 0]);
            float w1 = fmaxf(ex[g * 4 + 1], R * ey[g * 4 + 1]);
            float w2 = fmaxf(ex[g * 4 + 2], R * ey[g * 4 + 2]);
            float w3 = fmaxf(ex[g * 4 + 3], R * ey[g * 4 + 3]);
            w0 = (A.x > 0) ? w0 : 0.f;
            w1 = (A.y > 0) ? w1 : 0.f;
            w2 = (A.z > 0) ? w2 : 0.f;
            w3 = (A.w > 0) ? w3 : 0.f;
            w[g * 4 + 0] = w0; w[g * 4 + 1] = w1;
            w[g * 4 + 2] = w2; w[g * 4 + 3] = w3;
            z += (w0 + w1) + (w2 + w3);
        }
        // prefetch row r+2 into the buffer just consumed (before the barrier)
        if (r < 14) {
            const int4* nb = (const int4*)(adj + (size_t)(row0 + r + 2) * N);
#pragma unroll
            for (int g = 0; g < 4; g++) a4[r & 1][g] = __ldg(nb + g * 512 + t);
        }
        // block-wide row sum (double-buffered smem, one barrier per row)
#pragma unroll
        for (int o = 16; o; o >>= 1) z += __shfl_xor_sync(0xFFFFFFFFu, z, o);
        if (lane == 0) sZ[r & 1][warp] = z;
        __syncthreads();
        float zt = 0.f;
#pragma unroll
        for (int q = 0; q < 16; q++) zt += sZ[r & 1][q];
        float invZ = (zt > 0.f) ? (1.0f / zt) : 0.f;
#pragma unroll
        for (int k = 0; k < 16; k++) acc[k] = fmaf(w[k], invZ, acc[k]);
    }

    float4* part4 = (float4*)(g_part + (size_t)blockIdx.x * N);
#pragma unroll
    for (int g = 0; g < 4; g++)
        part4[g * 512 + t] = make_float4(acc[g * 4 + 0], acc[g * 4 + 1],
                                         acc[g * 4 + 2], acc[g * 4 + 3]);
}

// ---------------- deterministic column reduction (fp32 chunks, fp64 combine) ----
// 256 blocks x 256 threads. Block owns 32 columns; 8 chunk-threads per column,
// each sums 64 partials in fp32 (4-cyc chain, unroll-8 MLP); fixed-order fp64
// combine -> deterministic.
__global__ void __launch_bounds__(256) k_reduce() {
    __shared__ float sd[8][32];
    int t = threadIdx.x;
    int v = t & 31;            // column within block
    int u = t >> 5;            // chunk 0..7
    int c = blockIdx.x * 32 + v;
    float s = 0.f;
    int b0 = u * 64;
#pragma unroll 8
    for (int b = b0; b < b0 + 64; b++)
        s += g_part[(size_t)b * N + c];
    sd[u][v] = s;
    __syncthreads();
    if (u == 0) {
        double tot = 0.0;
#pragma unroll
        for (int q = 0; q < 8; q++) tot += (double)sd[q][v];   // fixed order
        g_colsumf[c] = (float)tot;
    }
}

// ---------------- exact top-512 via brute-force ranking (FLOAT out) ----------------
// 512 blocks x 256 threads; block owns 16 j's; 16 segment-threads per j (512 each).
__global__ void __launch_bounds__(256) k_rank(float* __restrict__ out) {
    __shared__ uint32_t sc[N];
    __shared__ int sr[256];
    int t = threadIdx.x;
    const float4* cs4 = (const float4*)g_colsumf;
    uint4* sc4 = (uint4*)sc;
#pragma unroll
    for (int p = 0; p < N / 4 / 256; p++) {
        float4 v = __ldg(cs4 + p * 256 + t);
        sc4[p * 256 + t] = make_uint4(__float_as_uint(v.x), __float_as_uint(v.y),
                                      __float_as_uint(v.z), __float_as_uint(v.w));
    }
    __syncthreads();

    int jl  = t & 15;
    int seg = t >> 4;          // 0..15, 512 elements each
    int j = blockIdx.x * 16 + jl;
    uint32_t sj = sc[j];
    int rank = 0;
    int p0 = seg * (N / 16);
#pragma unroll 4
    for (int p = p0; p < p0 + N / 16; p++) {
        uint32_t sp = sc[p];
        rank += (sp > sj) || (sp == sj && p < j);
    }
    sr[t] = rank;
    __syncthreads();
    if (t < 16) {
        int total = 0;
#pragma unroll
        for (int s = 0; s < 16; s++) total += sr[t + 16 * s];
        if (total < SS) out[total] = (float)j;     // float index (output dtype is f32)
    }
}

// ---------------- launch ----------------
extern "C" void kernel_launch(void* const* d_in, const int* in_sizes, int n_in,
                              void* d_out, int out_size) {
    const float* input = nullptr;
    const int*   adj   = nullptr;
    const float* W     = nullptr;
    const float* a     = nullptr;
    for (int i = 0; i < n_in; i++) {
        long long s = in_sizes[i];
        if      (s == (long long)N * IN_F)     input = (const float*)d_in[i];
        else if (s == (long long)N * N)        adj   = (const int*)d_in[i];
        else if (s == (long long)IN_F * OUT_F) W     = (const float*)d_in[i];
        else if (s == 2 * OUT_F)               a     = (const float*)d_in[i];
    }
    if (!input || !adj || !W || !a) {
        input = (const float*)d_in[0];
        adj   = (const int*)d_in[1];
        W     = (const float*)d_in[2];
        a     = (const float*)d_in[3];
    }
    float* out = (float*)d_out;

    k_wa<<<1, IN_F>>>(W, a);
    k_s<<<N / 8, 256>>>(input);
    k_main<<<512, 512>>>(adj);
    k_reduce<<<N / 32, 256>>>();
    k_rank<<<N / 16, 256>>>(out);
}